// round 1
// baseline (speedup 1.0000x reference)
#include <cuda_runtime.h>
#include <math.h>

#define FD   1024
#define SEM  300
#define NWAY 5
#define BS   32
#define NB   512
#define NQ   75
#define BTOT (BS*NWAY)     // 160
#define CATD (FD+SEM)      // 1324

// ---------------- scratch (device globals: no allocation allowed) ----------------
__device__ float g_s1  [BTOT*SEM];
__device__ float g_scal[BTOT*SEM];
__device__ float g_avg [BS*CATD];
__device__ float g_gv  [BS*FD];
__device__ float g_gs  [BS*SEM];
__device__ float g_q   [BTOT*FD];
__device__ float g_qkg [BTOT*FD];
__device__ float g_qksg[BTOT*SEM];
__device__ float g_scr [BTOT*NB];
__device__ float g_mix [BTOT*FD];
__device__ float g_outv[BTOT*FD];
__device__ float g_out [BTOT*FD];
__device__ float g_fake[BS*FD];

// ---------------- generic tiled fp32 GEMM ----------------
// C[M,N] = A[M,K] @ B  (B is [K,N] if !BT, [N,K] if BT)
// epi: 0 none, 1 leaky(0.1), 2 sigmoid+1, 3 multiply gate[(m/NWAY)*gateN + n]
// acc: if set, C += result (bias/epi applied to the GEMM term before add)
template<bool BT>
__global__ void gemm_k(const float* __restrict__ A, const float* __restrict__ B,
                       const float* __restrict__ bias, float* __restrict__ C,
                       int M, int N, int K, int epi,
                       const float* __restrict__ gate, int gateN, int acc)
{
    __shared__ float As[32][33];
    __shared__ float Bs[32][65];
    int tid = threadIdx.x;
    int tx = tid & 31, ty = tid >> 5;
    int m0 = blockIdx.y * 32, n0 = blockIdx.x * 64;
    float accv[4][2] = {{0.f,0.f},{0.f,0.f},{0.f,0.f},{0.f,0.f}};

    for (int k0 = 0; k0 < K; k0 += 32) {
        #pragma unroll
        for (int p = 0; p < 4; p++) {
            int i = ty + 8*p, j = tx;
            As[i][j] = (m0+i < M && k0+j < K) ? A[(size_t)(m0+i)*K + k0+j] : 0.f;
        }
        if (!BT) {
            int n = tid & 63, kb = tid >> 6;
            #pragma unroll
            for (int p = 0; p < 8; p++) {
                int kk = kb + 4*p;
                Bs[kk][n] = (k0+kk < K && n0+n < N) ? B[(size_t)(k0+kk)*N + n0+n] : 0.f;
            }
        } else {
            int kk = tid & 31, nb = tid >> 5;
            #pragma unroll
            for (int p = 0; p < 8; p++) {
                int n = nb + 8*p;
                Bs[kk][n] = (n0+n < N && k0+kk < K) ? B[(size_t)(n0+n)*K + k0+kk] : 0.f;
            }
        }
        __syncthreads();
        #pragma unroll
        for (int k = 0; k < 32; k++) {
            float b0 = Bs[k][tx], b1 = Bs[k][tx+32];
            #pragma unroll
            for (int r = 0; r < 4; r++) {
                float a = As[ty*4+r][k];
                accv[r][0] += a*b0;
                accv[r][1] += a*b1;
            }
        }
        __syncthreads();
    }

    #pragma unroll
    for (int r = 0; r < 4; r++) {
        int m = m0 + ty*4 + r;
        if (m >= M) continue;
        #pragma unroll
        for (int cc = 0; cc < 2; cc++) {
            int n = n0 + tx + 32*cc;
            if (n >= N) continue;
            float v = accv[r][cc];
            if (bias) v += bias[n];
            if (epi == 1)      v = (v >= 0.f) ? v : 0.1f*v;
            else if (epi == 2) v = 1.f + 1.f/(1.f + __expf(-v));
            else if (epi == 3) v *= gate[(size_t)(m/NWAY)*gateN + n];
            size_t idx = (size_t)m*N + n;
            if (acc) v += C[idx];
            C[idx] = v;
        }
    }
}

// ---------------- avg over base bank: avg[b, 0:1024]=mean(bw), [1024:1324]=mean(bsm) ----------------
__global__ void avg_k(const float* __restrict__ bw, const float* __restrict__ bsm,
                      float* __restrict__ avg)
{
    int b = blockIdx.x;
    int c = blockIdx.y*128 + threadIdx.x;
    if (c >= CATD) return;
    float s = 0.f;
    if (c < FD) {
        const float* p = bw + (size_t)b*NB*FD + c;
        for (int n = 0; n < NB; n++) s += p[(size_t)n*FD];
    } else {
        const float* p = bsm + (size_t)b*NB*SEM + (c-FD);
        for (int n = 0; n < NB; n++) s += p[(size_t)n*SEM];
    }
    avg[b*CATD + c] = s * (1.f/NB);
}

// ---------------- scores[bB,n] = (qkg[bB]·bw[b,n] + qksg[bB]·bsm[b,n]) / 32 ----------------
__global__ void scores_k(const float* __restrict__ qkg, const float* __restrict__ qksg,
                         const float* __restrict__ bw, const float* __restrict__ bsm,
                         float* __restrict__ scr)
{
    __shared__ float qv[NWAY][FD];
    __shared__ float qs[NWAY][SEM];
    int b = blockIdx.x;
    int tid = threadIdx.x;  // 256
    for (int i = tid; i < NWAY*FD; i += 256)
        qv[i/FD][i%FD] = qkg[(size_t)(b*NWAY + i/FD)*FD + (i%FD)];
    for (int i = tid; i < NWAY*SEM; i += 256)
        qs[i/SEM][i%SEM] = qksg[(size_t)(b*NWAY + i/SEM)*SEM + (i%SEM)];
    __syncthreads();

    int lane = tid & 31, w = tid >> 5;  // 8 warps
    for (int it = 0; it < 8; it++) {
        int n = blockIdx.y*64 + w*8 + it;
        float a0=0.f,a1=0.f,a2=0.f,a3=0.f,a4=0.f;
        const float* row = bw + ((size_t)(b*NB + n))*FD;
        for (int i = lane; i < FD; i += 32) {
            float x = row[i];
            a0 += x*qv[0][i]; a1 += x*qv[1][i]; a2 += x*qv[2][i];
            a3 += x*qv[3][i]; a4 += x*qv[4][i];
        }
        const float* rs = bsm + ((size_t)(b*NB + n))*SEM;
        for (int i = lane; i < SEM; i += 32) {
            float x = rs[i];
            a0 += x*qs[0][i]; a1 += x*qs[1][i]; a2 += x*qs[2][i];
            a3 += x*qs[3][i]; a4 += x*qs[4][i];
        }
        #pragma unroll
        for (int off = 16; off; off >>= 1) {
            a0 += __shfl_xor_sync(0xffffffffu, a0, off);
            a1 += __shfl_xor_sync(0xffffffffu, a1, off);
            a2 += __shfl_xor_sync(0xffffffffu, a2, off);
            a3 += __shfl_xor_sync(0xffffffffu, a3, off);
            a4 += __shfl_xor_sync(0xffffffffu, a4, off);
        }
        if (lane == 0) {
            const float inv = 1.f/32.f;  // 1/sqrt(1024)
            scr[(size_t)(b*NWAY+0)*NB + n] = a0*inv;
            scr[(size_t)(b*NWAY+1)*NB + n] = a1*inv;
            scr[(size_t)(b*NWAY+2)*NB + n] = a2*inv;
            scr[(size_t)(b*NWAY+3)*NB + n] = a3*inv;
            scr[(size_t)(b*NWAY+4)*NB + n] = a4*inv;
        }
    }
}

// ---------------- softmax over 512, in place ----------------
__global__ void softmax_k(float* __restrict__ scr)
{
    __shared__ float red[NB];
    int r = blockIdx.x, t = threadIdx.x;
    float v = scr[(size_t)r*NB + t];
    red[t] = v; __syncthreads();
    for (int s = NB/2; s; s >>= 1) { if (t < s) red[t] = fmaxf(red[t], red[t+s]); __syncthreads(); }
    float mx = red[0]; __syncthreads();
    float e = __expf(v - mx);
    red[t] = e; __syncthreads();
    for (int s = NB/2; s; s >>= 1) { if (t < s) red[t] += red[t+s]; __syncthreads(); }
    scr[(size_t)r*NB + t] = e / red[0];
}

// ---------------- mix[bB,f] = (sum_n attn[bB,n]*bw[b,n,f]) * gv[b,f] ----------------
__global__ void mix_k(const float* __restrict__ attn, const float* __restrict__ bw,
                      const float* __restrict__ gv, float* __restrict__ mix)
{
    __shared__ float at[NWAY][NB];
    int b = blockIdx.x;
    int t = threadIdx.x;  // 128
    for (int i = t; i < NWAY*NB; i += 128)
        at[i/NB][i%NB] = attn[(size_t)(b*NWAY + i/NB)*NB + (i%NB)];
    __syncthreads();
    int f = blockIdx.y*128 + t;
    float a0=0.f,a1=0.f,a2=0.f,a3=0.f,a4=0.f;
    const float* p = bw + (size_t)b*NB*FD + f;
    for (int n = 0; n < NB; n++) {
        float x = p[(size_t)n*FD];
        a0 += x*at[0][n]; a1 += x*at[1][n]; a2 += x*at[2][n];
        a3 += x*at[3][n]; a4 += x*at[4][n];
    }
    float g = gv[b*FD + f];
    mix[(size_t)(b*NWAY+0)*FD + f] = a0*g;
    mix[(size_t)(b*NWAY+1)*FD + f] = a1*g;
    mix[(size_t)(b*NWAY+2)*FD + f] = a2*g;
    mix[(size_t)(b*NWAY+3)*FD + f] = a3*g;
    mix[(size_t)(b*NWAY+4)*FD + f] = a4*g;
}

// ---------------- fake[b,f] = mean over nway of out ----------------
__global__ void fake_k(const float* __restrict__ outp, float* __restrict__ fake)
{
    int b = blockIdx.x;
    int f = blockIdx.y*128 + threadIdx.x;
    float s = 0.f;
    #pragma unroll
    for (int c = 0; c < NWAY; c++) s += outp[(size_t)(b*NWAY+c)*FD + f];
    fake[(size_t)b*FD + f] = s * (1.f/NWAY);
}

// ---------------- cosine metric logits ----------------
__global__ void logits_k(const float* __restrict__ scen, const float* __restrict__ fake,
                         const float* __restrict__ qf, const float* __restrict__ temp_p,
                         float* __restrict__ outL)
{
    __shared__ float pr[NWAY+1][FD];
    __shared__ float pinv[NWAY+1];
    int b = blockIdx.x;
    int t = threadIdx.x;  // 512
    for (int i = t; i < (NWAY+1)*FD; i += 512) {
        int c = i/FD, f = i%FD;
        pr[c][f] = (c < NWAY) ? scen[(size_t)(b*NWAY+c)*FD + f] : fake[(size_t)b*FD + f];
    }
    __syncthreads();
    int lane = t & 31, w = t >> 5;  // 16 warps
    if (w < NWAY+1) {
        float s = 0.f;
        for (int i = lane; i < FD; i += 32) { float x = pr[w][i]; s += x*x; }
        #pragma unroll
        for (int off = 16; off; off >>= 1) s += __shfl_xor_sync(0xffffffffu, s, off);
        if (lane == 0) pinv[w] = 1.f/sqrtf(s);
    }
    __syncthreads();
    if (w >= 15) return;
    int iq = blockIdx.y*15 + w;
    const float* q = qf + (size_t)(b*NQ + iq)*FD;
    float qq=0.f,d0=0.f,d1=0.f,d2=0.f,d3=0.f,d4=0.f,d5=0.f;
    for (int i = lane; i < FD; i += 32) {
        float x = q[i];
        qq += x*x;
        d0 += x*pr[0][i]; d1 += x*pr[1][i]; d2 += x*pr[2][i];
        d3 += x*pr[3][i]; d4 += x*pr[4][i]; d5 += x*pr[5][i];
    }
    #pragma unroll
    for (int off = 16; off; off >>= 1) {
        qq += __shfl_xor_sync(0xffffffffu, qq, off);
        d0 += __shfl_xor_sync(0xffffffffu, d0, off);
        d1 += __shfl_xor_sync(0xffffffffu, d1, off);
        d2 += __shfl_xor_sync(0xffffffffu, d2, off);
        d3 += __shfl_xor_sync(0xffffffffu, d3, off);
        d4 += __shfl_xor_sync(0xffffffffu, d4, off);
        d5 += __shfl_xor_sync(0xffffffffu, d5, off);
    }
    if (lane == 0) {
        float tv = *temp_p;
        float s = tv / sqrtf(qq);
        float* o = outL + (size_t)(b*NQ + iq)*6;
        o[0] = d0*s*pinv[0]; o[1] = d1*s*pinv[1]; o[2] = d2*s*pinv[2];
        o[3] = d3*s*pinv[3]; o[4] = d4*s*pinv[4]; o[5] = d5*s*pinv[5];
    }
}

// ---------------- host ----------------
static float* getsym(const void* s) {
    void* p = nullptr;
    cudaGetSymbolAddress(&p, s);
    return (float*)p;
}

extern "C" void kernel_launch(void* const* d_in, const int* in_sizes, int n_in,
                              void* d_out, int out_size)
{
    const float* sc   = (const float*)d_in[0];
    const float* bw   = (const float*)d_in[1];
    const float* ss   = (const float*)d_in[2];
    const float* bsm  = (const float*)d_in[3];
    const float* qf   = (const float*)d_in[4];
    const float* Wm1  = (const float*)d_in[5];
    const float* bm1  = (const float*)d_in[6];
    const float* Wm2  = (const float*)d_in[7];
    const float* bm2  = (const float*)d_in[8];
    const float* Wvis = (const float*)d_in[9];
    const float* bvis = (const float*)d_in[10];
    const float* Wsem = (const float*)d_in[11];
    const float* bsem = (const float*)d_in[12];
    const float* Wq   = (const float*)d_in[13];
    const float* Wk   = (const float*)d_in[14];
    const float* Wv   = (const float*)d_in[15];
    const float* Wqs  = (const float*)d_in[16];
    const float* Wks  = (const float*)d_in[17];
    const float* Wfc  = (const float*)d_in[18];
    const float* temp = (const float*)d_in[19];
    float* out = (float*)d_out;

    float* s1p   = getsym(g_s1);
    float* sp    = getsym(g_scal);
    float* avgp  = getsym(g_avg);
    float* gvp   = getsym(g_gv);
    float* gsp   = getsym(g_gs);
    float* qp    = getsym(g_q);
    float* qkgp  = getsym(g_qkg);
    float* qksgp = getsym(g_qksg);
    float* scrp  = getsym(g_scr);
    float* mixp  = getsym(g_mix);
    float* outvp = getsym(g_outv);
    float* outp  = getsym(g_out);
    float* fakep = getsym(g_fake);

    auto grd = [](int M, int N) { return dim3((unsigned)((N+63)/64), (unsigned)((M+31)/32)); };

    // semantic calibration MLP
    gemm_k<false><<<grd(BTOT,SEM), 256>>>(ss,  Wm1, bm1, s1p, BTOT, SEM, SEM, 1, nullptr, 0, 0);
    gemm_k<false><<<grd(BTOT,SEM), 256>>>(s1p, Wm2, bm2, sp,  BTOT, SEM, SEM, 0, nullptr, 0, 0);
    // task-average + gates (per-b only: base bank is broadcast over nway)
    avg_k<<<dim3(BS,(CATD+127)/128), 128>>>(bw, bsm, avgp);
    gemm_k<false><<<grd(BS,FD),  256>>>(avgp, Wvis, bvis, gvp, BS, FD,  CATD, 2, nullptr, 0, 0);
    gemm_k<false><<<grd(BS,SEM), 256>>>(avgp, Wsem, bsem, gsp, BS, SEM, CATD, 2, nullptr, 0, 0);
    // q projection
    gemm_k<false><<<grd(BTOT,FD), 256>>>(sc, Wq,  nullptr, qp, BTOT, FD, FD,  0, nullptr, 0, 0);
    gemm_k<false><<<grd(BTOT,FD), 256>>>(sp, Wqs, nullptr, qp, BTOT, FD, SEM, 0, nullptr, 0, 1);
    // pull K-projection onto q: qkg = (q @ Wk^T) * g_v,  qksg = (q @ Wks^T) * g_s
    gemm_k<true ><<<grd(BTOT,FD),  256>>>(qp, Wk,  nullptr, qkgp,  BTOT, FD,  FD, 3, gvp, FD,  0);
    gemm_k<true ><<<grd(BTOT,SEM), 256>>>(qp, Wks, nullptr, qksgp, BTOT, SEM, FD, 3, gsp, SEM, 0);
    // attention against the raw base bank (gates folded into q-side)
    scores_k<<<dim3(BS, NB/64), 256>>>(qkgp, qksgp, bw, bsm, scrp);
    softmax_k<<<BTOT, NB>>>(scrp);
    mix_k<<<dim3(BS, FD/128), 128>>>(scrp, bw, gvp, mixp);
    // project mixed vector through Wv then Wfc, with residual
    gemm_k<false><<<grd(BTOT,FD), 256>>>(mixp, Wv, nullptr, outvp, BTOT, FD, FD, 0, nullptr, 0, 0);
    cudaMemcpyAsync(outp, sc, (size_t)BTOT*FD*sizeof(float), cudaMemcpyDeviceToDevice, 0);
    gemm_k<false><<<grd(BTOT,FD), 256>>>(outvp, Wfc, nullptr, outp, BTOT, FD, FD, 0, nullptr, 0, 1);
    // fake prototype + cosine logits
    fake_k<<<dim3(BS, FD/128), 128>>>(outp, fakep);
    logits_k<<<dim3(BS, NQ/15), 512>>>(sc, fakep, qf, temp, out);
}

// round 2
// speedup vs baseline: 1.4843x; 1.4843x over previous
#include <cuda_runtime.h>
#include <math.h>

#define FD   1024
#define SEM  300
#define NWAY 5
#define BS   32
#define NB   512
#define NQ   75
#define BTOT (BS*NWAY)     // 160
#define CATD (FD+SEM)      // 1324

// ---------------- scratch (device globals) ----------------
__device__ float g_s1  [BTOT*SEM];
__device__ float g_scal[BTOT*SEM];
__device__ float g_avg [BS*CATD];
__device__ float g_gv  [BS*FD];
__device__ float g_gs  [BS*SEM];
__device__ float g_q   [BTOT*FD];
__device__ float g_qkg [BTOT*FD];
__device__ float g_qksg[BTOT*SEM];
__device__ float g_scr [BTOT*NB];
__device__ float g_mix [BTOT*FD];
__device__ float g_outv[BTOT*FD];
__device__ float g_out [BTOT*FD];
__device__ float g_BT  [FD*CATD];        // transposed [Wk;Wks] : [1024,1324]
__device__ float g_part[8*BTOT*CATD];    // split-K partials (max 8*160*1324)

// ---------------- famA: column-parallel split-K skinny GEMM ----------------
// part[z][M][N] = A[M,K-chunk_z] @ B[K-chunk_z, N]
// A(m,k) = k<K1 ? A1[m,k] : A2[m,k-K1]
// KSPLIT=true : B(k,n) = k<K1 ? B1[k*N+n]  : B2[(k-K1)*N+n]   (concat along K)
// KSPLIT=false: B(k,n) = n<N1 ? B1[k*N1+n] : B2[k*(N-N1)+(n-N1)] (concat along N)
template<bool KSPLIT>
__global__ void famA_k(const float* __restrict__ A1, const float* __restrict__ A2, int K1,
                       const float* __restrict__ B1, const float* __restrict__ B2, int N1,
                       float* __restrict__ part,
                       int M, int N, int K, int tpz)
{
    __shared__ float As[32][36];   // [k][m], padded: rows 16B-aligned, reads broadcast
    int tid = threadIdx.x;
    int n  = blockIdx.x*256 + tid;
    int m0 = blockIdx.y*32;
    int kbeg = blockIdx.z * tpz * 32;
    int kend = min(K, kbeg + tpz*32);

    float acc[32];
    #pragma unroll
    for (int r=0;r<32;r++) acc[r]=0.f;

    bool nok = (n < N);
    const float* Bcol = nullptr; int ldb = 0;
    if (!KSPLIT) {
        if (n < N1) { Bcol = B1 + n;        ldb = N1;     }
        else        { Bcol = B2 + (n - N1); ldb = N - N1; }
    }

    for (int k0 = kbeg; k0 < kend; k0 += 32) {
        #pragma unroll
        for (int e=0;e<4;e++) {
            int idx = tid + e*256;
            int mm = idx >> 5, kk = idx & 31;
            int m_g = m0 + mm, k_g = k0 + kk;
            float v = 0.f;
            if (m_g < M && k_g < K)
                v = (k_g < K1) ? A1[(size_t)m_g*K1 + k_g]
                               : A2[(size_t)m_g*(K-K1) + (k_g-K1)];
            As[kk][mm] = v;
        }
        __syncthreads();
        if (nok) {
            const float* bp; int bstr;
            if (KSPLIT) {
                if (k0 < K1) { bp = B1 + (size_t)k0*N + n;      bstr = N; }
                else         { bp = B2 + (size_t)(k0-K1)*N + n; bstr = N; }
            } else { bp = Bcol + (size_t)k0*ldb; bstr = ldb; }
            int kmax = min(32, kend - k0);
            if (kmax == 32) {
                #pragma unroll
                for (int kk=0;kk<32;kk++) {
                    float w = bp[(size_t)kk*bstr];
                    const float4* ar = reinterpret_cast<const float4*>(&As[kk][0]);
                    #pragma unroll
                    for (int r4=0;r4<8;r4++) {
                        float4 a = ar[r4];
                        acc[r4*4+0] = fmaf(w, a.x, acc[r4*4+0]);
                        acc[r4*4+1] = fmaf(w, a.y, acc[r4*4+1]);
                        acc[r4*4+2] = fmaf(w, a.z, acc[r4*4+2]);
                        acc[r4*4+3] = fmaf(w, a.w, acc[r4*4+3]);
                    }
                }
            } else {
                for (int kk=0;kk<kmax;kk++) {
                    float w = bp[(size_t)kk*bstr];
                    const float4* ar = reinterpret_cast<const float4*>(&As[kk][0]);
                    #pragma unroll
                    for (int r4=0;r4<8;r4++) {
                        float4 a = ar[r4];
                        acc[r4*4+0] = fmaf(w, a.x, acc[r4*4+0]);
                        acc[r4*4+1] = fmaf(w, a.y, acc[r4*4+1]);
                        acc[r4*4+2] = fmaf(w, a.z, acc[r4*4+2]);
                        acc[r4*4+3] = fmaf(w, a.w, acc[r4*4+3]);
                    }
                }
            }
        }
        __syncthreads();
    }
    if (nok) {
        size_t base = (size_t)blockIdx.z * M * N + n;
        #pragma unroll
        for (int r=0;r<32;r++) {
            int m = m0 + r;
            if (m < M) part[base + (size_t)m*N] = acc[r];
        }
    }
}

// ---------------- split-K reduce + epilogue ----------------
// epi: 0 none, 1 leaky(0.1), 2 sigmoid+1, 3 gate-mult (gate[(m/NWAY)*width + n'])
__global__ void red_k(const float* __restrict__ part, int Z, int M, int N, int N1,
                      const float* __restrict__ bias1, const float* __restrict__ bias2,
                      int epi,
                      const float* __restrict__ gate1, const float* __restrict__ gate2,
                      const float* __restrict__ res,
                      float* __restrict__ out1, float* __restrict__ out2)
{
    int i = blockIdx.x*256 + threadIdx.x;
    if (i >= M*N) return;
    int m = i / N, n = i % N;
    float v = 0.f;
    for (int z=0; z<Z; z++) v += part[(size_t)z*M*N + i];
    bool first = n < N1;
    int nn = first ? n : n - N1;
    int w  = first ? N1 : N - N1;
    const float* bias = first ? bias1 : bias2;
    if (bias) v += bias[nn];
    if (epi == 1)      v = (v >= 0.f) ? v : 0.1f*v;
    else if (epi == 2) v = 1.f + 1.f/(1.f + __expf(-v));
    else if (epi == 3) v *= (first ? gate1 : gate2)[(size_t)(m/NWAY)*w + nn];
    if (res) v += res[(size_t)m*N1 + n];
    if (first) out1[(size_t)m*N1 + n] = v;
    else       out2[(size_t)m*(N-N1) + nn] = v;
}

// ---------------- transpose [Wk;Wks] into BT[1024][1324] ----------------
__global__ void transpose_k(const float* __restrict__ Wk, const float* __restrict__ Wks,
                            float* __restrict__ BT)
{
    __shared__ float t[32][33];
    int n0 = blockIdx.x*32, k0 = blockIdx.y*32;
    int lx = threadIdx.x & 31, ly = threadIdx.x >> 5;   // 256 threads
    #pragma unroll
    for (int i=ly;i<32;i+=8) {
        int n = n0+i, k = k0+lx;
        float v = 0.f;
        if (n < CATD) v = (n < FD) ? Wk[(size_t)n*FD + k] : Wks[(size_t)(n-FD)*FD + k];
        t[i][lx] = v;
    }
    __syncthreads();
    #pragma unroll
    for (int i=ly;i<32;i+=8) {
        int k = k0+i, n = n0+lx;
        if (n < CATD) BT[(size_t)k*CATD + n] = t[lx][i];
    }
}

// ---------------- avg over base bank ----------------
__global__ void avg_k(const float* __restrict__ bw, const float* __restrict__ bsm,
                      float* __restrict__ avg)
{
    int b = blockIdx.x;
    int c = blockIdx.y*256 + threadIdx.x;
    if (c >= CATD) return;
    float s = 0.f;
    if (c < FD) {
        const float* p = bw + (size_t)b*NB*FD + c;
        #pragma unroll 8
        for (int n = 0; n < NB; n++) s += p[(size_t)n*FD];
    } else {
        const float* p = bsm + (size_t)b*NB*SEM + (c-FD);
        #pragma unroll 8
        for (int n = 0; n < NB; n++) s += p[(size_t)n*SEM];
    }
    avg[b*CATD + c] = s * (1.f/NB);
}

// ---------------- scores: register-tiled, warp handles 8 base rows ----------------
__global__ void scores_k(const float* __restrict__ qkg, const float* __restrict__ qksg,
                         const float* __restrict__ bw, const float* __restrict__ bsm,
                         float* __restrict__ scr)
{
    int b = blockIdx.x;
    int w = threadIdx.x >> 5, lane = threadIdx.x & 31;   // 8 warps
    int nbase = blockIdx.y*64 + w*8;
    float acc[8][5];
    #pragma unroll
    for (int j=0;j<8;j++)
        #pragma unroll
        for (int p=0;p<5;p++) acc[j][p]=0.f;

    const float4* qkg4  = (const float4*)qkg  + (size_t)b*NWAY*(FD/4);
    const float4* qksg4 = (const float4*)qksg + (size_t)b*NWAY*(SEM/4);
    const float4* bw4   = (const float4*)bw   + (size_t)b*NB*(FD/4);
    const float4* bsm4  = (const float4*)bsm  + (size_t)b*NB*(SEM/4);

    // FD part: 256 float4 per row, 8 tiles of 32
    #pragma unroll
    for (int t=0;t<8;t++) {
        int c = t*32 + lane;
        float4 qv[5];
        #pragma unroll
        for (int p=0;p<5;p++) qv[p] = qkg4[p*(FD/4) + c];
        #pragma unroll
        for (int j=0;j<8;j++) {
            float4 x = bw4[(size_t)(nbase+j)*(FD/4) + c];
            #pragma unroll
            for (int p=0;p<5;p++)
                acc[j][p] += x.x*qv[p].x + x.y*qv[p].y + x.z*qv[p].z + x.w*qv[p].w;
        }
    }
    // SEM part: 75 float4 per row, 3 guarded tiles
    #pragma unroll
    for (int t=0;t<3;t++) {
        int c = t*32 + lane;
        bool ok = c < (SEM/4);
        float4 qv[5];
        #pragma unroll
        for (int p=0;p<5;p++)
            qv[p] = ok ? qksg4[p*(SEM/4) + c] : make_float4(0.f,0.f,0.f,0.f);
        #pragma unroll
        for (int j=0;j<8;j++) {
            float4 x = ok ? bsm4[(size_t)(nbase+j)*(SEM/4) + c] : make_float4(0.f,0.f,0.f,0.f);
            #pragma unroll
            for (int p=0;p<5;p++)
                acc[j][p] += x.x*qv[p].x + x.y*qv[p].y + x.z*qv[p].z + x.w*qv[p].w;
        }
    }
    #pragma unroll
    for (int off=16; off; off>>=1)
        #pragma unroll
        for (int j=0;j<8;j++)
            #pragma unroll
            for (int p=0;p<5;p++)
                acc[j][p] += __shfl_xor_sync(0xffffffffu, acc[j][p], off);
    const float inv = 1.f/32.f;   // 1/sqrt(1024)
    #pragma unroll
    for (int j=0;j<8;j++) {
        if (lane == j) {
            int n = nbase + j;
            #pragma unroll
            for (int p=0;p<5;p++)
                scr[(size_t)(b*NWAY+p)*NB + n] = acc[j][p]*inv;
        }
    }
}

// ---------------- softmax over 512, in place ----------------
__global__ void softmax_k(float* __restrict__ scr)
{
    __shared__ float red[NB];
    int r = blockIdx.x, t = threadIdx.x;
    float v = scr[(size_t)r*NB + t];
    red[t] = v; __syncthreads();
    for (int s = NB/2; s; s >>= 1) { if (t < s) red[t] = fmaxf(red[t], red[t+s]); __syncthreads(); }
    float mx = red[0]; __syncthreads();
    float e = __expf(v - mx);
    red[t] = e; __syncthreads();
    for (int s = NB/2; s; s >>= 1) { if (t < s) red[t] += red[t+s]; __syncthreads(); }
    scr[(size_t)r*NB + t] = e / red[0];
}

// ---------------- mix[bB,f] = (sum_n attn[bB,n]*bw[b,n,f]) * gv[b,f] ----------------
__global__ void mix_k(const float* __restrict__ attn, const float* __restrict__ bw,
                      const float* __restrict__ gv, float* __restrict__ mix)
{
    __shared__ float at[NWAY][NB];
    int b = blockIdx.x;
    int t = threadIdx.x;  // 128
    for (int i = t; i < NWAY*NB; i += 128)
        at[i/NB][i%NB] = attn[(size_t)(b*NWAY + i/NB)*NB + (i%NB)];
    __syncthreads();
    int f = blockIdx.y*128 + t;
    float a0=0.f,a1=0.f,a2=0.f,a3=0.f,a4=0.f;
    const float* p = bw + (size_t)b*NB*FD + f;
    #pragma unroll 8
    for (int n = 0; n < NB; n++) {
        float x = p[(size_t)n*FD];
        a0 += x*at[0][n]; a1 += x*at[1][n]; a2 += x*at[2][n];
        a3 += x*at[3][n]; a4 += x*at[4][n];
    }
    float g = gv[b*FD + f];
    mix[(size_t)(b*NWAY+0)*FD + f] = a0*g;
    mix[(size_t)(b*NWAY+1)*FD + f] = a1*g;
    mix[(size_t)(b*NWAY+2)*FD + f] = a2*g;
    mix[(size_t)(b*NWAY+3)*FD + f] = a3*g;
    mix[(size_t)(b*NWAY+4)*FD + f] = a4*g;
}

// ---------------- cosine metric logits (fake folded in) ----------------
__global__ void logits_k(const float* __restrict__ scen, const float* __restrict__ outp,
                         const float* __restrict__ qf, const float* __restrict__ temp_p,
                         float* __restrict__ outL)
{
    __shared__ float pr[NWAY+1][FD];
    __shared__ float pinv[NWAY+1];
    int b = blockIdx.x;
    int t = threadIdx.x;  // 512
    for (int f = t; f < FD; f += 512) {
        float s = 0.f;
        #pragma unroll
        for (int c = 0; c < NWAY; c++) {
            pr[c][f] = scen[(size_t)(b*NWAY+c)*FD + f];
            s += outp[(size_t)(b*NWAY+c)*FD + f];
        }
        pr[NWAY][f] = s * (1.f/NWAY);
    }
    __syncthreads();
    int lane = t & 31, w = t >> 5;  // 16 warps
    if (w < NWAY+1) {
        float s = 0.f;
        for (int i = lane; i < FD; i += 32) { float x = pr[w][i]; s += x*x; }
        #pragma unroll
        for (int off = 16; off; off >>= 1) s += __shfl_xor_sync(0xffffffffu, s, off);
        if (lane == 0) pinv[w] = 1.f/sqrtf(s);
    }
    __syncthreads();
    if (w >= 15) return;
    int iq = blockIdx.y*15 + w;
    const float* q = qf + (size_t)(b*NQ + iq)*FD;
    float qq=0.f,d0=0.f,d1=0.f,d2=0.f,d3=0.f,d4=0.f,d5=0.f;
    for (int i = lane; i < FD; i += 32) {
        float x = q[i];
        qq += x*x;
        d0 += x*pr[0][i]; d1 += x*pr[1][i]; d2 += x*pr[2][i];
        d3 += x*pr[3][i]; d4 += x*pr[4][i]; d5 += x*pr[5][i];
    }
    #pragma unroll
    for (int off = 16; off; off >>= 1) {
        qq += __shfl_xor_sync(0xffffffffu, qq, off);
        d0 += __shfl_xor_sync(0xffffffffu, d0, off);
        d1 += __shfl_xor_sync(0xffffffffu, d1, off);
        d2 += __shfl_xor_sync(0xffffffffu, d2, off);
        d3 += __shfl_xor_sync(0xffffffffu, d3, off);
        d4 += __shfl_xor_sync(0xffffffffu, d4, off);
        d5 += __shfl_xor_sync(0xffffffffu, d5, off);
    }
    if (lane == 0) {
        float tv = *temp_p;
        float s = tv / sqrtf(qq);
        float* o = outL + (size_t)(b*NQ + iq)*6;
        o[0] = d0*s*pinv[0]; o[1] = d1*s*pinv[1]; o[2] = d2*s*pinv[2];
        o[3] = d3*s*pinv[3]; o[4] = d4*s*pinv[4]; o[5] = d5*s*pinv[5];
    }
}

// ---------------- host ----------------
static float* getsym(const void* s) {
    void* p = nullptr;
    cudaGetSymbolAddress(&p, s);
    return (float*)p;
}

extern "C" void kernel_launch(void* const* d_in, const int* in_sizes, int n_in,
                              void* d_out, int out_size)
{
    const float* sc   = (const float*)d_in[0];
    const float* bw   = (const float*)d_in[1];
    const float* ss   = (const float*)d_in[2];
    const float* bsm  = (const float*)d_in[3];
    const float* qf   = (const float*)d_in[4];
    const float* Wm1  = (const float*)d_in[5];
    const float* bm1  = (const float*)d_in[6];
    const float* Wm2  = (const float*)d_in[7];
    const float* bm2  = (const float*)d_in[8];
    const float* Wvis = (const float*)d_in[9];
    const float* bvis = (const float*)d_in[10];
    const float* Wsem = (const float*)d_in[11];
    const float* bsem = (const float*)d_in[12];
    const float* Wq   = (const float*)d_in[13];
    const float* Wk   = (const float*)d_in[14];
    const float* Wv   = (const float*)d_in[15];
    const float* Wqs  = (const float*)d_in[16];
    const float* Wks  = (const float*)d_in[17];
    const float* Wfc  = (const float*)d_in[18];
    const float* temp = (const float*)d_in[19];
    float* out = (float*)d_out;

    float* s1p   = getsym(g_s1);
    float* sp    = getsym(g_scal);
    float* avgp  = getsym(g_avg);
    float* gvp   = getsym(g_gv);
    float* gsp   = getsym(g_gs);
    float* qp    = getsym(g_q);
    float* qkgp  = getsym(g_qkg);
    float* qksgp = getsym(g_qksg);
    float* scrp  = getsym(g_scr);
    float* mixp  = getsym(g_mix);
    float* outvp = getsym(g_outv);
    float* outp  = getsym(g_out);
    float* btp   = getsym(g_BT);
    float* partp = getsym(g_part);

    auto gx  = [](int N) { return (unsigned)((N+255)/256); };
    auto gy  = [](int M) { return (unsigned)((M+31)/32); };
    auto rg  = [](int M, int N) { return (unsigned)((M*N+255)/256); };

    // 0. transpose [Wk;Wks] (independent of everything else)
    transpose_k<<<dim3((CATD+31)/32, FD/32), 256>>>(Wk, Wks, btp);

    // 1. map_sem MLP layer 1: s1 = leaky(ss@Wm1 + bm1)
    famA_k<false><<<dim3(gx(SEM), gy(BTOT), 5), 256>>>(ss, nullptr, SEM, Wm1, nullptr, SEM, partp, BTOT, SEM, SEM, 2);
    red_k<<<rg(BTOT,SEM), 256>>>(partp, 5, BTOT, SEM, SEM, bm1, nullptr, 1, nullptr, nullptr, nullptr, s1p, nullptr);
    // 2. layer 2: s = s1@Wm2 + bm2
    famA_k<false><<<dim3(gx(SEM), gy(BTOT), 5), 256>>>(s1p, nullptr, SEM, Wm2, nullptr, SEM, partp, BTOT, SEM, SEM, 2);
    red_k<<<rg(BTOT,SEM), 256>>>(partp, 5, BTOT, SEM, SEM, bm2, nullptr, 0, nullptr, nullptr, nullptr, sp, nullptr);

    // 3. task average of base bank (per-b)
    avg_k<<<dim3(BS, (CATD+255)/256), 256>>>(bw, bsm, avgp);

    // 4. gates: [gv|gs] = sigmoid(avg @ [Wvis|Wsem] + [bvis|bsem]) + 1   (N-concat)
    famA_k<false><<<dim3(gx(CATD), gy(BS), 12), 256>>>(avgp, nullptr, CATD, Wvis, Wsem, FD, partp, BS, CATD, CATD, 4);
    red_k<<<rg(BS,CATD), 256>>>(partp, 12, BS, CATD, FD, bvis, bsem, 2, nullptr, nullptr, nullptr, gvp, gsp);

    // 5. q = sc@Wq + s@Wqs   (K-concat: A=[sc|s], B=[Wq;Wqs])
    famA_k<true><<<dim3(gx(FD), gy(BTOT), 8), 256>>>(sc, sp, FD, Wq, Wqs, FD, partp, BTOT, FD, CATD, 6);
    red_k<<<rg(BTOT,FD), 256>>>(partp, 8, BTOT, FD, FD, nullptr, nullptr, 0, nullptr, nullptr, nullptr, qp, nullptr);

    // 6. [qkg|qksg] = (q @ BT) * [gv|gs]   (BT = [Wk;Wks]^T, gates in reduce)
    famA_k<false><<<dim3(gx(CATD), gy(BTOT), 8), 256>>>(qp, nullptr, FD, btp, nullptr, CATD, partp, BTOT, CATD, FD, 4);
    red_k<<<rg(BTOT,CATD), 256>>>(partp, 8, BTOT, CATD, FD, nullptr, nullptr, 3, gvp, gsp, nullptr, qkgp, qksgp);

    // 7. attention scores vs raw base bank
    scores_k<<<dim3(BS, NB/64), 256>>>(qkgp, qksgp, bw, bsm, scrp);
    softmax_k<<<BTOT, NB>>>(scrp);
    mix_k<<<dim3(BS, FD/128), 128>>>(scrp, bw, gvp, mixp);

    // 8. outv = mix@Wv ; out = outv@Wfc + sc
    famA_k<false><<<dim3(gx(FD), gy(BTOT), 8), 256>>>(mixp, nullptr, FD, Wv, nullptr, FD, partp, BTOT, FD, FD, 4);
    red_k<<<rg(BTOT,FD), 256>>>(partp, 8, BTOT, FD, FD, nullptr, nullptr, 0, nullptr, nullptr, nullptr, outvp, nullptr);
    famA_k<false><<<dim3(gx(FD), gy(BTOT), 8), 256>>>(outvp, nullptr, FD, Wfc, nullptr, FD, partp, BTOT, FD, FD, 4);
    red_k<<<rg(BTOT,FD), 256>>>(partp, 8, BTOT, FD, FD, nullptr, nullptr, 0, nullptr, nullptr, sc, outp, nullptr);

    // 9. fake prototype (folded) + cosine logits
    logits_k<<<dim3(BS, NQ/15), 512>>>(sc, outp, qf, temp, out);
}